// round 5
// baseline (speedup 1.0000x reference)
#include <cuda_runtime.h>
#include <cstdint>
#include <cstddef>

// ---------------------------------------------------------------------------
// GRU stack: 4 layers (256 -> 256), B=128, T=384, reset_after=True (Keras).
// Phase A (per layer): xp = X @ W + b_in   (fp32 GEMM, scalar FFMA, dbl-buffer)
// Phase B (per layer): persistent scan, 8-CTA clusters per batch tile,
//                      weights in SMEM, h exchanged via DSMEM st.async,
//                      f32x2 packed FMA inner loop.
// ---------------------------------------------------------------------------

#define BATCH   128
#define T_STEPS 384
#define UNITS   256
#define G3      768
#define MROWS   (BATCH * T_STEPS)   // 49152

__device__ float g_xp[MROWS * G3];      // [B*T, 768] input projections
__device__ float g_hseq[MROWS * UNITS]; // [B*T, 256] hidden sequence

// ---------------------------------------------------------------------------
// f32x2 packed math helpers (scan only)
// ---------------------------------------------------------------------------
typedef unsigned long long ull;

__device__ __forceinline__ ull p2(float x, float y) {
    ull d; asm("mov.b64 %0, {%1, %2};" : "=l"(d) : "f"(x), "f"(y)); return d;
}
__device__ __forceinline__ ull p1(float x) {
    ull d; asm("mov.b64 %0, {%1, %1};" : "=l"(d) : "f"(x)); return d;
}
__device__ __forceinline__ void fma2(ull& acc, ull a, ull b) {
    asm("fma.rn.f32x2 %0, %1, %2, %0;" : "+l"(acc) : "l"(a), "l"(b));
}
__device__ __forceinline__ void add2(ull& acc, ull a) {
    asm("add.rn.f32x2 %0, %1, %0;" : "+l"(acc) : "l"(a));
}
__device__ __forceinline__ float2 unp2(ull d) {
    float2 v; asm("mov.b64 {%0, %1}, %2;" : "=f"(v.x), "=f"(v.y) : "l"(d)); return v;
}

// ---------------------------------------------------------------------------
// cluster / mbarrier helpers
// ---------------------------------------------------------------------------
__device__ __forceinline__ uint32_t smem_u32(const void* p) {
    uint32_t a;
    asm("{ .reg .u64 t; cvta.to.shared.u64 t, %1; cvt.u32.u64 %0, t; }"
        : "=r"(a) : "l"(p));
    return a;
}
__device__ __forceinline__ uint32_t mapa_u32(uint32_t a, uint32_t rank) {
    uint32_t r;
    asm("mapa.shared::cluster.u32 %0, %1, %2;" : "=r"(r) : "r"(a), "r"(rank));
    return r;
}
__device__ __forceinline__ void mbar_init(uint32_t a, uint32_t cnt) {
    asm volatile("mbarrier.init.shared.b64 [%0], %1;" :: "r"(a), "r"(cnt) : "memory");
}
__device__ __forceinline__ void mbar_expect(uint32_t a, uint32_t bytes) {
    asm volatile("mbarrier.arrive.expect_tx.shared.b64 _, [%0], %1;"
                 :: "r"(a), "r"(bytes) : "memory");
}
__device__ __forceinline__ void mbar_arrive_remote(uint32_t a) {
    asm volatile("mbarrier.arrive.shared::cluster.b64 _, [%0];" :: "r"(a) : "memory");
}
// bounded wait: if the protocol ever wedges we return (wrong answer visible to
// the harness, not a container timeout).
__device__ __forceinline__ void mbar_wait_cluster(uint32_t a, int parity) {
    unsigned ok = 0;
    for (int i = 0; i < 1000000; i++) {
        asm volatile(
            "{\n\t.reg .pred P;\n\t"
            "mbarrier.try_wait.parity.acquire.cluster.shared::cta.b64 P, [%1], %2, 0x2000;\n\t"
            "selp.u32 %0, 1, 0, P;\n\t}"
            : "=r"(ok) : "r"(a), "r"((unsigned)parity) : "memory");
        if (ok) break;
    }
}
__device__ __forceinline__ void st_async_b64(uint32_t raddr, ull v, uint32_t rmbar) {
    asm volatile("st.async.shared::cluster.mbarrier::complete_tx::bytes.b64 [%0], %1, [%2];"
                 :: "r"(raddr), "l"(v), "r"(rmbar) : "memory");
}
#define CLUSTER_SYNC_() do {                                          \
    asm volatile("barrier.cluster.arrive.aligned;" ::: "memory");     \
    asm volatile("barrier.cluster.wait.aligned;" ::: "memory");       \
} while (0)

__device__ __forceinline__ float sigm_(float x) {
    return 1.f / (1.f + __expf(-x));
}
__device__ __forceinline__ float tanh_(float x) {
    float s = 1.f / (1.f + __expf(-2.f * x));
    return 2.f * s - 1.f;
}

// ---------------------------------------------------------------------------
// SGEMM: C[M=49152, N=768] = A[M,256] @ W[256,768] + bias_in[768]
// 128x128x8 tiles, 256 threads, 8x8 SCALAR register tile, 2-stage dbl buffer.
// (Exact R2 version: measured 359us, fma=67.5%, regs=125, no spills.)
// ---------------------------------------------------------------------------
__global__ __launch_bounds__(256, 2) void gemm_kernel(
    const float* __restrict__ X,
    const float* __restrict__ W,
    const float* __restrict__ bin,
    int use_x)
{
    const int K = 256, N = G3;
    const float* A = use_x ? X : g_hseq;

    __shared__ float As[2][8][128];
    __shared__ float Bs[2][8][128];

    int tid = threadIdx.x;
    int tx = tid & 15;
    int ty = tid >> 4;
    int bm = blockIdx.y * 128;
    int bn = blockIdx.x * 128;

    float acc[8][8];
#pragma unroll
    for (int i = 0; i < 8; i++)
#pragma unroll
        for (int j = 0; j < 8; j++) acc[i][j] = 0.f;

    int arow = tid >> 1;
    int acol = (tid & 1) * 4;
    int brow = tid >> 5;
    int bcol = (tid & 31) * 4;

    const float* Ap = A + (size_t)(bm + arow) * K + acol;
    const float* Wp = W + (size_t)brow * N + bn + bcol;

    {
        float4 a4 = *(const float4*)(Ap);
        float4 b4 = *(const float4*)(Wp);
        As[0][acol + 0][arow] = a4.x;
        As[0][acol + 1][arow] = a4.y;
        As[0][acol + 2][arow] = a4.z;
        As[0][acol + 3][arow] = a4.w;
        *(float4*)&Bs[0][brow][bcol] = b4;
    }
    __syncthreads();

    int buf = 0;
    for (int k0 = 8; k0 <= K; k0 += 8) {
        float4 a4n, b4n;
        if (k0 < K) {
            a4n = *(const float4*)(Ap + k0);
            b4n = *(const float4*)(Wp + (size_t)k0 * N);
        }
#pragma unroll
        for (int kk = 0; kk < 8; kk++) {
            float ra[8], rb[8];
            *(float4*)(ra)     = *(const float4*)&As[buf][kk][ty * 4];
            *(float4*)(ra + 4) = *(const float4*)&As[buf][kk][64 + ty * 4];
            *(float4*)(rb)     = *(const float4*)&Bs[buf][kk][tx * 4];
            *(float4*)(rb + 4) = *(const float4*)&Bs[buf][kk][64 + tx * 4];
#pragma unroll
            for (int i = 0; i < 8; i++)
#pragma unroll
                for (int j = 0; j < 8; j++)
                    acc[i][j] += ra[i] * rb[j];
        }
        if (k0 < K) {
            int nb = buf ^ 1;
            As[nb][acol + 0][arow] = a4n.x;
            As[nb][acol + 1][arow] = a4n.y;
            As[nb][acol + 2][arow] = a4n.z;
            As[nb][acol + 3][arow] = a4n.w;
            *(float4*)&Bs[nb][brow][bcol] = b4n;
            __syncthreads();
            buf = nb;
        }
    }

#pragma unroll
    for (int i = 0; i < 8; i++) {
        int row = (i < 4) ? (ty * 4 + i) : (64 + ty * 4 + (i - 4));
#pragma unroll
        for (int jh = 0; jh < 2; jh++) {
            int col = jh * 64 + tx * 4;
            float4 v;
            v.x = acc[i][jh * 4 + 0] + bin[bn + col + 0];
            v.y = acc[i][jh * 4 + 1] + bin[bn + col + 1];
            v.z = acc[i][jh * 4 + 2] + bin[bn + col + 2];
            v.w = acc[i][jh * 4 + 3] + bin[bn + col + 3];
            *(float4*)&g_xp[(size_t)(bm + row) * N + bn + col] = v;
        }
    }
}

// ---------------------------------------------------------------------------
// Recurrent scan (unchanged from R4 — working protocol).
// Grid (8,16); cluster (8,1,1) = the 8 unit-tile CTAs of one batch tile.
// ---------------------------------------------------------------------------
#define OFF_MBAR 0       // full[0]@0, full[1]@8, empty[0]@16, empty[1]@24
#define OFF_W    128     // 6144 float4 = 98304 B  (w4[kp][g][up])
#define OFF_H    98432   // sh2[2][128 kp][8 rows] float2 = 16384 B
#define OFF_RED  114816  // red[8 ks][32 lane][13] u64 = 26624 B
#define SCAN_SMEM (OFF_RED + 26624)

__global__ __launch_bounds__(256, 1) __cluster_dims__(8, 1, 1)
void scan_kernel(const float* __restrict__ RK,    // [256, 768]
                 const float* __restrict__ brec)  // [768]
{
    extern __shared__ char smem[];
    const int tid = threadIdx.x;
    const int ut = blockIdx.x;          // cluster rank
    const int bt = blockIdx.y;
    const int u0 = ut * 32;
    const int b0 = bt * 8;

    const uint32_t sbase = smem_u32(smem);
    float4* sW = (float4*)(smem + OFF_W);
    ull* red = (ull*)(smem + OFF_RED);

    for (int i = tid; i < 6144; i += 256) {
        int kp = i / 48;
        int rem = i - kp * 48;
        int g = rem >> 4;
        int up = rem & 15;
        const float* s0 = RK + (size_t)(2 * kp) * G3 + g * 256 + u0 + 2 * up;
        float2 a = *(const float2*)s0;
        float2 b = *(const float2*)(s0 + G3);
        sW[i] = make_float4(a.x, a.y, b.x, b.y);
    }
    {
        float4* z = (float4*)(smem + OFF_H);
        for (int i = tid; i < 8192 / 16; i += 256) z[i] = make_float4(0, 0, 0, 0);
    }
    if (tid == 0) {
        mbar_init(sbase + 0, 1);    // full[0]
        mbar_init(sbase + 8, 1);    // full[1]
        mbar_init(sbase + 16, 8);   // empty[0]
        mbar_init(sbase + 24, 8);   // empty[1]
        asm volatile("fence.mbarrier_init.release.cluster;" ::: "memory");
        mbar_expect(sbase + 8, 8192);   // pre-arm full[1] for the h(0) fill
    }
    __syncthreads();
    CLUSTER_SYNC_();

    const int ks = tid >> 5;
    const int lane = tid & 31;
    const int bg = lane >> 4;
    const int up = lane & 15;
    const int kp0 = ks * 16;

    const int fb = tid >> 4;
    const int fu = tid & 15;
    const int bgF = fb >> 2;
    const int rF = fb & 3;

    float2 bzv = make_float2(0, 0), brv = make_float2(0, 0), bhv = make_float2(0, 0);
    if (tid < 128) {
        bzv = *(const float2*)(brec + 0   + u0 + 2 * fu);
        brv = *(const float2*)(brec + 256 + u0 + 2 * fu);
        bhv = *(const float2*)(brec + 512 + u0 + 2 * fu);
    }

    int fullp[2] = {0, 0};
    int emptyp[2] = {0, 1};

    for (int t = 0; t < T_STEPS; t++) {
        const int v = t & 1;
        const int w = v ^ 1;

        float2 mzv, mrv, mhv;
        if (tid < 128) {
            const float* xr = g_xp + ((size_t)(b0 + fb) * T_STEPS + t) * G3;
            mzv = *(const float2*)(xr + 0   + u0 + 2 * fu);
            mrv = *(const float2*)(xr + 256 + u0 + 2 * fu);
            mhv = *(const float2*)(xr + 512 + u0 + 2 * fu);
        }

        if (t > 0) { mbar_wait_cluster(sbase + v * 8, fullp[v]); fullp[v] ^= 1; }

        ull acc[4][3];
#pragma unroll
        for (int r = 0; r < 4; r++)
#pragma unroll
            for (int g = 0; g < 3; g++) acc[r][g] = 0ull;

        const char* hbuf = smem + OFF_H + v * 8192;
#pragma unroll 4
        for (int kp = kp0; kp < kp0 + 16; kp++) {
            float4 hA = *(const float4*)(hbuf + kp * 64 + bg * 32);
            float4 hB = *(const float4*)(hbuf + kp * 64 + bg * 32 + 16);
            ull h0[4], h1[4];
            h0[0] = p1(hA.x); h1[0] = p1(hA.y);
            h0[1] = p1(hA.z); h1[1] = p1(hA.w);
            h0[2] = p1(hB.x); h1[2] = p1(hB.y);
            h0[3] = p1(hB.z); h1[3] = p1(hB.w);
#pragma unroll
            for (int g = 0; g < 3; g++) {
                float4 wv = sW[kp * 48 + g * 16 + up];
                ull w01 = p2(wv.x, wv.y);
                ull w23 = p2(wv.z, wv.w);
#pragma unroll
                for (int r = 0; r < 4; r++) {
                    fma2(acc[r][g], h0[r], w01);
                    fma2(acc[r][g], h1[r], w23);
                }
            }
        }

        float2 hp = make_float2(0, 0);
        if (tid < 128)
            hp = *(const float2*)(hbuf + ((ut * 16 + fu) * 8 + fb) * 8);

        {
            ull* my = red + (size_t)(ks * 32 + lane) * 13;
#pragma unroll
            for (int g = 0; g < 3; g++)
#pragma unroll
                for (int r = 0; r < 4; r++)
                    my[g * 4 + r] = acc[r][g];
        }
        __syncthreads();

        if (tid == 0 && t <= T_STEPS - 3) {
            mbar_expect(sbase + v * 8, 8192);
            uint32_t emb = sbase + 16 + v * 8;
#pragma unroll
            for (int c = 0; c < 8; c++)
                mbar_arrive_remote(mapa_u32(emb, c));
        }

        if (tid < 128) {
            ull s[3];
#pragma unroll
            for (int g = 0; g < 3; g++) {
                ull a = red[(size_t)(bgF * 16 + fu) * 13 + g * 4 + rF];
#pragma unroll
                for (int k2 = 1; k2 < 8; k2++)
                    add2(a, red[(size_t)(k2 * 32 + bgF * 16 + fu) * 13 + g * 4 + rF]);
                s[g] = a;
            }
            float2 az = unp2(s[0]);
            float2 ar = unp2(s[1]);
            float2 ah = unp2(s[2]);

            float z0 = sigm_(mzv.x + az.x + bzv.x);
            float r0 = sigm_(mrv.x + ar.x + brv.x);
            float c0 = tanh_(mhv.x + r0 * (ah.x + bhv.x));
            float hn0 = z0 * hp.x + (1.f - z0) * c0;

            float z1 = sigm_(mzv.y + az.y + bzv.y);
            float r1 = sigm_(mrv.y + ar.y + brv.y);
            float c1 = tanh_(mhv.y + r1 * (ah.y + bhv.y));
            float hn1 = z1 * hp.y + (1.f - z1) * c1;

            *(float2*)(g_hseq + ((size_t)(b0 + fb) * T_STEPS + t) * UNITS + u0 + 2 * fu)
                = make_float2(hn0, hn1);

            if (t <= T_STEPS - 2) {
                mbar_wait_cluster(sbase + 16 + w * 8, emptyp[w]); emptyp[w] ^= 1;
                ull hn = p2(hn0, hn1);
                uint32_t dl = sbase + OFF_H + w * 8192 + ((ut * 16 + fu) * 8 + fb) * 8;
                uint32_t ml = sbase + w * 8;
#pragma unroll
                for (int c = 0; c < 8; c++)
                    st_async_b64(mapa_u32(dl, c), hn, mapa_u32(ml, c));
            }
        }
    }
    CLUSTER_SYNC_();
}

// ---------------------------------------------------------------------------
__global__ void copy_out_kernel(float* __restrict__ out) {
    int i = blockIdx.x * 256 + threadIdx.x;
    int b = i >> 8;
    int u = i & 255;
    out[i] = g_hseq[((size_t)b * T_STEPS + (T_STEPS - 1)) * UNITS + u];
}

// ---------------------------------------------------------------------------
extern "C" void kernel_launch(void* const* d_in, const int* in_sizes, int n_in,
                              void* d_out, int out_size) {
    (void)in_sizes; (void)n_in; (void)out_size;
    const float* x     = (const float*)d_in[0];
    const float* k0    = (const float*)d_in[1];
    const float* rk0   = (const float*)d_in[2];
    const float* b0    = (const float*)d_in[3];
    const float* kern  = (const float*)d_in[4];
    const float* rkern = (const float*)d_in[5];
    const float* bias  = (const float*)d_in[6];
    float* out = (float*)d_out;

    cudaFuncSetAttribute(scan_kernel,
        cudaFuncAttributeMaxDynamicSharedMemorySize, SCAN_SMEM);

    dim3 ggrid(G3 / 128, MROWS / 128);
    dim3 sgrid(8, 16);

    gemm_kernel<<<ggrid, 256>>>(x, k0, b0, 1);
    scan_kernel<<<sgrid, 256, SCAN_SMEM>>>(rk0, b0 + G3);

    for (int l = 0; l < 3; l++) {
        gemm_kernel<<<ggrid, 256>>>(nullptr, kern + (size_t)l * 256 * G3,
                                    bias + (size_t)l * 2 * G3, 0);
        scan_kernel<<<sgrid, 256, SCAN_SMEM>>>(rkern + (size_t)l * 256 * G3,
                                    bias + (size_t)l * 2 * G3 + G3);
    }

    copy_out_kernel<<<BATCH, 256>>>(out);
}